// round 15
// baseline (speedup 1.0000x reference)
#include <cuda_runtime.h>

#define NN 50000
#define EE 800000
#define RP_PAD (98 * 512)   // padded rowptr length (98 scan blocks x 512)
#define NSHARD 8
#define SHARD_N (NN / NSHARD)   // 6250

typedef unsigned long long ull;

// ---------------- device scratch (static allocations only) ----------------
__device__ float g_q[NN * 64];
__device__ float g_kv[NN * 128];     // interleaved: [n][cp*4 + {k0,k1,v0,v1}]
__device__ float g_skip[NN * 64];
__device__ float g_u[NN * 64];
__device__ float g_h[NN * 64];
__device__ float g_M[3][64 * 64];    // folded Wq*We per layer
__device__ float g_bu[3][64];
__device__ int   g_rowptr[RP_PAD];
__device__ int   g_cursor[NN];
__device__ int2  g_se[EE];           // (src, eid) in CSR order
__device__ int   g_part[128];
__device__ int   g_ticket[3 * NSHARD];  // sharded warp work-queues

// ---------------- packed f32x2 helpers (sm_103a fma.rn.f32x2) -------------
__device__ __forceinline__ ull pk2(float x, float y) {
    ull r; asm("mov.b64 %0, {%1,%2};" : "=l"(r) : "f"(x), "f"(y)); return r;
}
__device__ __forceinline__ ull dup2(float x) { return pk2(x, x); }
__device__ __forceinline__ void up2(ull a, float& x, float& y) {
    asm("mov.b64 {%0,%1}, %2;" : "=f"(x), "=f"(y) : "l"(a));
}
__device__ __forceinline__ ull fma2(ull a, ull b, ull c) {
    ull d; asm("fma.rn.f32x2 %0, %1, %2, %3;" : "=l"(d) : "l"(a), "l"(b), "l"(c)); return d;
}
__device__ __forceinline__ ull add2(ull a, ull b) {
    ull d; asm("add.rn.f32x2 %0, %1, %2;" : "=l"(d) : "l"(a), "l"(b)); return d;
}
__device__ __forceinline__ ull mul2(ull a, ull b) {
    ull d; asm("mul.rn.f32x2 %0, %1, %2;" : "=l"(d) : "l"(a), "l"(b)); return d;
}

// ---------------- fold body -------------------------------------------------
__device__ __forceinline__ void fold_body(int idx, const float* Wq, const float* bq,
                                          const float* We, int H, int layer) {
    if (idx < 4096) {
        int i = idx >> 6, j = idx & 63;
        float s = 0.f;
        if (H == 2) {
            int h = j >> 5, d = j & 31;
            for (int c = 0; c < 32; c++)
                s += Wq[i * 64 + h * 32 + c] * We[d * 64 + h * 32 + c];
        } else {
            int d = j & 31;
            for (int c = 0; c < 64; c++)
                s += Wq[i * 64 + c] * We[d * 64 + c];
            s *= 0.5f;
        }
        g_M[layer][idx] = s;
    }
    if (idx < 64) {
        int j = idx;
        float s = 0.f;
        if (H == 2) {
            int h = j >> 5, d = j & 31;
            for (int c = 0; c < 32; c++)
                s += bq[h * 32 + c] * We[d * 64 + h * 32 + c];
        } else {
            int d = j & 31;
            for (int c = 0; c < 64; c++)
                s += bq[c] * We[d * 64 + c];
            s *= 0.5f;
        }
        g_bu[layer][j] = s;
    }
}

// zero rowptr (padded) + tickets, and compute ALL THREE layer folds
__global__ void k_zerofold(
    const float* __restrict__ Wq0, const float* __restrict__ bq0, const float* __restrict__ We0,
    const float* __restrict__ Wq1, const float* __restrict__ bq1, const float* __restrict__ We1,
    const float* __restrict__ Wq2, const float* __restrict__ bq2, const float* __restrict__ We2)
{
    int idx = blockIdx.x * blockDim.x + threadIdx.x;
    if (idx < RP_PAD) g_rowptr[idx] = 0;
    if (idx < 3 * NSHARD) g_ticket[idx] = 0;
    if (idx < 4096) {
        fold_body(idx, Wq0, bq0, We0, 2, 0);
        fold_body(idx, Wq1, bq1, We1, 2, 1);
        fold_body(idx, Wq2, bq2, We2, 1, 2);
    }
}

// ---------------- CSR build (128-thr blocks: co-resident with GEMM) --------
__global__ __launch_bounds__(128) void k_hist(const int* __restrict__ dst) {
    int i = blockIdx.x * blockDim.x + threadIdx.x;
    if (i < EE) atomicAdd(&g_rowptr[dst[i] + 1], 1);
}

// 98 blocks x 128 threads, 4 elements/thread (512/block)
__global__ __launch_bounds__(128) void k_scanA() {
    __shared__ int sw[128];
    int b = blockIdx.x, t = threadIdx.x;
    int base = b * 512 + t * 4;
    int4 v = *(const int4*)&g_rowptr[base];
    int e0 = (base + 0 <= NN) ? v.x : 0;
    int e1 = (base + 1 <= NN) ? v.y : 0;
    int e2 = (base + 2 <= NN) ? v.z : 0;
    int e3 = (base + 3 <= NN) ? v.w : 0;
    int s1 = e0 + e1, s2 = s1 + e2, s3 = s2 + e3;
    sw[t] = s3;
    __syncthreads();
#pragma unroll
    for (int off = 1; off < 128; off <<= 1) {
        int tv = (t >= off) ? sw[t - off] : 0;
        __syncthreads();
        sw[t] += tv;
        __syncthreads();
    }
    int excl = (t > 0) ? sw[t - 1] : 0;
    int4 o;
    o.x = excl + e0; o.y = excl + s1; o.z = excl + s2; o.w = excl + s3;
    *(int4*)&g_rowptr[base] = o;
    if (t == 127) g_part[b] = sw[127];
}

__global__ __launch_bounds__(128) void k_scanC(int nb) {
    __shared__ int sp[128];
    int b = blockIdx.x, t = threadIdx.x;
    sp[t] = (t < nb) ? g_part[t] : 0;
    __syncthreads();
#pragma unroll
    for (int off = 1; off < 128; off <<= 1) {
        int tv = (t >= off) ? sp[t - off] : 0;
        __syncthreads();
        sp[t] += tv;
        __syncthreads();
    }
    int excl = (b == 0) ? 0 : sp[b - 1];
    int base = b * 512 + t * 4;
    int4 v = *(const int4*)&g_rowptr[base];
    v.x += excl; v.y += excl; v.z += excl; v.w += excl;
    *(int4*)&g_rowptr[base] = v;
    if (base + 0 < NN) g_cursor[base + 0] = v.x;
    if (base + 1 < NN) g_cursor[base + 1] = v.y;
    if (base + 2 < NN) g_cursor[base + 2] = v.z;
    if (base + 3 < NN) g_cursor[base + 3] = v.w;
}

__global__ __launch_bounds__(128) void k_scatter(const int* __restrict__ src, const int* __restrict__ dst) {
    int i = blockIdx.x * blockDim.x + threadIdx.x;
    if (i < EE) {
        int d = dst[i];
        int pos = atomicAdd(&g_cursor[d], 1);
        g_se[pos] = make_int2(src[i], i);
    }
}

// ---------------- node GEMM: R8 tile + double-buffered x staging -----------
#define XS_STRIDE (64 * 36)
#define GEMM_SMEM_FLOATS (64 * 320 + 2 * XS_STRIDE)
__global__ __launch_bounds__(320, 2) void k_gemm(
    const float* __restrict__ xin, int in_is_gh, int layer,
    const float* __restrict__ Wq, const float* __restrict__ bq,
    const float* __restrict__ Wk, const float* __restrict__ bk,
    const float* __restrict__ Wv, const float* __restrict__ bv,
    const float* __restrict__ Ws, const float* __restrict__ bs)
{
    extern __shared__ float sm[];
    float* ws = sm;                  // [64][320]
    float* xs = sm + 64 * 320;       // 2 buffers of [64][36]

    const float* x = in_is_gh ? g_h : xin;
    int tid = threadIdx.x;
    int cg = tid >> 3;
    int ng = tid & 7;
    int m  = cg >> 3;
    int c8 = (cg & 7) * 8;
    int nbase = ng * 4;

    {
        const float* W;
        int wm = tid >> 6;
        if      (wm == 0) W = Wq;
        else if (wm == 1) W = Wk;
        else if (wm == 2) W = Wv;
        else if (wm == 3) W = Ws;
        else              W = &g_M[layer][0];
        int wc = tid & 63;
#pragma unroll
        for (int d = 0; d < 64; d++)
            ws[d * 320 + tid] = W[d * 64 + wc];
    }

    ull bacc[4];
    {
        const float* B;
        if      (m == 0) B = bq;
        else if (m == 1) B = bk;
        else if (m == 2) B = bv;
        else if (m == 3) B = bs;
        else             B = g_bu[layer];
#pragma unroll
        for (int cp = 0; cp < 4; cp++)
            bacc[cp] = pk2(B[c8 + 2 * cp], B[c8 + 2 * cp + 1]);
    }

    const int nstrips = (NN + 31) / 32;  // 1563

    int i0 = tid, i1 = tid + 320;
    int nl0 = i0 >> 4, c40 = i0 & 15;
    int nl1 = i1 >> 4, c41 = i1 & 15;

    int strip = blockIdx.x;
    if (strip < nstrips) {
        int n0 = strip * 32;
        {
            int row = n0 + nl0; if (row >= NN) row = NN - 1;
            float4 v = *(const float4*)&x[row * 64 + c40 * 4];
            float* dst = xs;
            dst[(c40 * 4 + 0) * 36 + nl0] = v.x;
            dst[(c40 * 4 + 1) * 36 + nl0] = v.y;
            dst[(c40 * 4 + 2) * 36 + nl0] = v.z;
            dst[(c40 * 4 + 3) * 36 + nl0] = v.w;
        }
        if (i1 < 512) {
            int row = n0 + nl1; if (row >= NN) row = NN - 1;
            float4 v = *(const float4*)&x[row * 64 + c41 * 4];
            float* dst = xs;
            dst[(c41 * 4 + 0) * 36 + nl1] = v.x;
            dst[(c41 * 4 + 1) * 36 + nl1] = v.y;
            dst[(c41 * 4 + 2) * 36 + nl1] = v.z;
            dst[(c41 * 4 + 3) * 36 + nl1] = v.w;
        }
    }

    int buf = 0;
    for (; strip < nstrips; strip += gridDim.x) {
        __syncthreads();

        int nstrip = strip + gridDim.x;
        float4 st0, st1;
        bool do1 = (i1 < 512);
        if (nstrip < nstrips) {
            int n0n = nstrip * 32;
            int row0 = n0n + nl0; if (row0 >= NN) row0 = NN - 1;
            st0 = *(const float4*)&x[row0 * 64 + c40 * 4];
            if (do1) {
                int row1 = n0n + nl1; if (row1 >= NN) row1 = NN - 1;
                st1 = *(const float4*)&x[row1 * 64 + c41 * 4];
            }
        }

        const float* xb = xs + buf * XS_STRIDE;

        ull acc[16];
#pragma unroll
        for (int n = 0; n < 4; n++)
#pragma unroll
            for (int cp = 0; cp < 4; cp++)
                acc[n * 4 + cp] = bacc[cp];

#pragma unroll 8
        for (int d = 0; d < 64; d++) {
            float4 xv = *(const float4*)&xb[d * 36 + nbase];
            const ulonglong2* wp = (const ulonglong2*)&ws[d * 320 + cg * 8];
            ulonglong2 w01 = wp[0];
            ulonglong2 w23 = wp[1];
            ull x0 = dup2(xv.x), x1 = dup2(xv.y), x2 = dup2(xv.z), x3 = dup2(xv.w);
            acc[0]  = fma2(x0, w01.x, acc[0]);
            acc[1]  = fma2(x0, w01.y, acc[1]);
            acc[2]  = fma2(x0, w23.x, acc[2]);
            acc[3]  = fma2(x0, w23.y, acc[3]);
            acc[4]  = fma2(x1, w01.x, acc[4]);
            acc[5]  = fma2(x1, w01.y, acc[5]);
            acc[6]  = fma2(x1, w23.x, acc[6]);
            acc[7]  = fma2(x1, w23.y, acc[7]);
            acc[8]  = fma2(x2, w01.x, acc[8]);
            acc[9]  = fma2(x2, w01.y, acc[9]);
            acc[10] = fma2(x2, w23.x, acc[10]);
            acc[11] = fma2(x2, w23.y, acc[11]);
            acc[12] = fma2(x3, w01.x, acc[12]);
            acc[13] = fma2(x3, w01.y, acc[13]);
            acc[14] = fma2(x3, w23.x, acc[14]);
            acc[15] = fma2(x3, w23.y, acc[15]);
        }

        int n0 = strip * 32;
#pragma unroll
        for (int n = 0; n < 4; n++) {
            int row = n0 + nbase + n; if (row >= NN) row = NN - 1;
            ull* a = &acc[n * 4];
            if (m == 1 || m == 2) {
                int off = (m == 1) ? 0 : 2;
#pragma unroll
                for (int cp = 0; cp < 4; cp++)
                    *(ull*)&g_kv[row * 128 + (c8 / 2 + cp) * 4 + off] = a[cp];
            } else {
                float* O = (m == 0) ? g_q : ((m == 3) ? g_skip : g_u);
                ulonglong2 s0; s0.x = a[0]; s0.y = a[1];
                ulonglong2 s1; s1.x = a[2]; s1.y = a[3];
                *(ulonglong2*)&O[row * 64 + c8] = s0;
                *(ulonglong2*)&O[row * 64 + c8 + 4] = s1;
            }
        }

        if (nstrip < nstrips) {
            float* dst = xs + (1 - buf) * XS_STRIDE;
            dst[(c40 * 4 + 0) * 36 + nl0] = st0.x;
            dst[(c40 * 4 + 1) * 36 + nl0] = st0.y;
            dst[(c40 * 4 + 2) * 36 + nl0] = st0.z;
            dst[(c40 * 4 + 3) * 36 + nl0] = st0.w;
            if (do1) {
                dst[(c41 * 4 + 0) * 36 + nl1] = st1.x;
                dst[(c41 * 4 + 1) * 36 + nl1] = st1.y;
                dst[(c41 * 4 + 2) * 36 + nl1] = st1.z;
                dst[(c41 * 4 + 3) * 36 + nl1] = st1.w;
            }
        }
        buf ^= 1;
    }
}

// ---------------- fused edge aggregation: sharded warp-ticket ---------------
// 8 ticket counters per layer, shard q = blockIdx & 7 owns nodes
// [q*6250, (q+1)*6250) -> 8x lower per-address atomic rate, same balance.
template <int H>
__global__ __launch_bounds__(256, 6) void k_edge_agg(
    const float* __restrict__ eattr,
    const float* __restrict__ We,
    float* __restrict__ out, int out_is_gh,
    const float* __restrict__ prelu, int apply_prelu, int layer)
{
    __shared__ __align__(16) float we_s[32 * 64];
    __shared__ __align__(16) float zs[8][64];

    int tid = threadIdx.x;
    int lane = tid & 31;
    int wslot = tid >> 5;
    int shard = blockIdx.x & (NSHARD - 1);
    int* tick = &g_ticket[layer * NSHARD + shard];
    int nodebase = shard * SHARD_N;

    for (int idx = tid; idx < 2048; idx += 256) we_s[idx] = We[idx];
    __syncthreads();

    float* o = out_is_gh ? g_h : out;
    const float scale = (H == 2) ? 0.17677669529663687f : 0.125f;
    const int eaoff = (2 * lane) & 31;
    const int kvo = lane * 4;
    const float aprelu = apply_prelu ? *prelu : 1.0f;

    int nraw = 0;
    if (lane == 0) nraw = atomicAdd(tick, 1);
    int nl = __shfl_sync(0xffffffffu, nraw, 0);

    while (nl < SHARD_N) {
        if (lane == 0) nraw = atomicAdd(tick, 1);
        int n = nodebase + nl;

        ull q2 = *(const ull*)&g_q[n * 64 + 2 * lane];
        ull u2 = *(const ull*)&g_u[n * 64 + 2 * lane];

        ull accv = 0, accz = 0;
        float s = 0.f;

        int beg = g_rowptr[n], end = g_rowptr[n + 1];
        int deg = end - beg;
        int npair = deg >> 1;

        ull k0 = 0, v0 = 0, e0 = 0, k1 = 0, v1 = 0, e1 = 0;

        if (npair > 0) {
            int2 i0 = g_se[beg], i1 = g_se[beg + 1];
            ulonglong2 kva = *(const ulonglong2*)&g_kv[i0.x * 128 + kvo];
            ulonglong2 kvb = *(const ulonglong2*)&g_kv[i1.x * 128 + kvo];
            k0 = kva.x; v0 = kva.y; k1 = kvb.x; v1 = kvb.y;
            e0 = *(const ull*)&eattr[(long)i0.y * 32 + eaoff];
            e1 = *(const ull*)&eattr[(long)i1.y * 32 + eaoff];
        }

        int i = beg;
        for (int p = 0; p < npair; p++) {
            ull ka = k0, va = v0, ea0 = e0;
            ull kb = k1, vb = v1, eb = e1;
            int j = i + 2;

            if (p + 1 < npair) {
                int2 i0 = g_se[j], i1 = g_se[j + 1];
                ulonglong2 kva = *(const ulonglong2*)&g_kv[i0.x * 128 + kvo];
                ulonglong2 kvb = *(const ulonglong2*)&g_kv[i1.x * 128 + kvo];
                k0 = kva.x; v0 = kva.y; k1 = kvb.x; v1 = kvb.y;
                e0 = *(const ull*)&eattr[(long)i0.y * 32 + eaoff];
                e1 = *(const ull*)&eattr[(long)i1.y * 32 + eaoff];
            }

            ull pa = add2(mul2(q2, ka), mul2(u2, ea0));
            ull pb = add2(mul2(q2, kb), mul2(u2, eb));
            float ax0, ay0, bx0, by0;
            up2(pa, ax0, ay0);
            up2(pb, bx0, by0);
            float pla = ax0 + ay0;
            float plb = bx0 + by0;
            pla += __shfl_xor_sync(0xffffffffu, pla, 1);
            plb += __shfl_xor_sync(0xffffffffu, plb, 1);
            pla += __shfl_xor_sync(0xffffffffu, pla, 2);
            plb += __shfl_xor_sync(0xffffffffu, plb, 2);
            pla += __shfl_xor_sync(0xffffffffu, pla, 4);
            plb += __shfl_xor_sync(0xffffffffu, plb, 4);
            pla += __shfl_xor_sync(0xffffffffu, pla, 8);
            plb += __shfl_xor_sync(0xffffffffu, plb, 8);
            if (H == 1) {
                pla += __shfl_xor_sync(0xffffffffu, pla, 16);
                plb += __shfl_xor_sync(0xffffffffu, plb, 16);
            }

            float w0 = __expf(pla * scale);
            float w1 = __expf(plb * scale);
            s += w0 + w1;

            ull w02 = dup2(w0), w12 = dup2(w1);
            accv = add2(accv, fma2(w02, va, mul2(w12, vb)));
            accz = add2(accz, fma2(w02, ea0, mul2(w12, eb)));
            i = j;
        }

        for (; i < end; i++) {
            int2 t = g_se[i];
            ulonglong2 kva = *(const ulonglong2*)&g_kv[t.x * 128 + kvo];
            ull ee = *(const ull*)&eattr[(long)t.y * 32 + eaoff];
            ull pa = add2(mul2(q2, kva.x), mul2(u2, ee));
            float ax0, ay0; up2(pa, ax0, ay0);
            float pla = ax0 + ay0;
            pla += __shfl_xor_sync(0xffffffffu, pla, 1);
            pla += __shfl_xor_sync(0xffffffffu, pla, 2);
            pla += __shfl_xor_sync(0xffffffffu, pla, 4);
            pla += __shfl_xor_sync(0xffffffffu, pla, 8);
            if (H == 1) pla += __shfl_xor_sync(0xffffffffu, pla, 16);
            float w0 = __expf(pla * scale);
            s += w0;
            ull w02 = dup2(w0);
            accv = fma2(w02, kva.y, accv);
            accz = fma2(w02, ee, accz);
        }

        float zx, zy; up2(accz, zx, zy);
        zs[wslot][2 * lane] = zx;
        zs[wslot][2 * lane + 1] = zy;
        __syncwarp();

        ull ze = 0;
        int base = (H == 2) ? ((lane >> 4) * 32) : 0;
#pragma unroll
        for (int d = 0; d < 32; d++) {
            ull wp = *(const ull*)&we_s[d * 64 + 2 * lane];
            ze = fma2(dup2(zs[wslot][base + d]), wp, ze);
        }
        __syncwarp();

        ull skip2 = *(const ull*)&g_skip[n * 64 + 2 * lane];
        float inv = (s > 0.f) ? 1.f / s : 0.f;
        float avx, avy; up2(accv, avx, avy);
        float ex, ey; up2(ze, ex, ey);
        float sx, sy; up2(skip2, sx, sy);
        float ox = (avx + ex) * inv + sx;
        float oy = (avy + ey) * inv + sy;
        if (apply_prelu) {
            ox = (ox >= 0.f) ? ox : aprelu * ox;
            oy = (oy >= 0.f) ? oy : aprelu * oy;
        }
        *(float2*)&o[n * 64 + 2 * lane] = make_float2(ox, oy);

        nl = __shfl_sync(0xffffffffu, nraw, 0);
    }
}

// ---------------- launch ----------------------------------------------------
extern "C" void kernel_launch(void* const* d_in, const int* in_sizes, int n_in,
                              void* d_out, int out_size)
{
    const float* x  = (const float*)d_in[0];
    const float* ea = (const float*)d_in[1];
    const int*   ei = (const int*)d_in[2];
    const int* src = ei;
    const int* dst = ei + EE;

    const float *Wq[3], *bq[3], *Wk[3], *bk[3], *Wv[3], *bv[3], *We[3], *Ws[3], *bs[3];
    for (int l = 0; l < 3; l++) {
        int b = 3 + 9 * l;
        Wq[l] = (const float*)d_in[b + 0];
        bq[l] = (const float*)d_in[b + 1];
        Wk[l] = (const float*)d_in[b + 2];
        bk[l] = (const float*)d_in[b + 3];
        Wv[l] = (const float*)d_in[b + 4];
        bv[l] = (const float*)d_in[b + 5];
        We[l] = (const float*)d_in[b + 6];
        Ws[l] = (const float*)d_in[b + 7];
        bs[l] = (const float*)d_in[b + 8];
    }
    const float* prelu = (const float*)d_in[30];
    float* out = (float*)d_out;

    const int NB = 98;            // scan blocks (512 elems each)
    const int AGG_BLOCKS = 888;   // 6 blocks/SM x 148 SMs (multiple of 8)
    const int GEMM_BLOCKS = 296;
    const int GEMM_SMEM = GEMM_SMEM_FLOATS * 4;  // 100352 B

    cudaFuncSetAttribute(k_gemm, cudaFuncAttributeMaxDynamicSharedMemorySize, GEMM_SMEM);

    // fork/join: CSR chain (128-thr blocks, RF-co-resident) overlaps gemm0
    cudaStream_t s2;
    cudaStreamCreateWithFlags(&s2, cudaStreamNonBlocking);
    cudaEvent_t e0, e1;
    cudaEventCreateWithFlags(&e0, cudaEventDisableTiming);
    cudaEventCreateWithFlags(&e1, cudaEventDisableTiming);

    // 1: zero rowptr+tickets + all folds (root of both branches)
    k_zerofold<<<(RP_PAD + 255) / 256, 256>>>(Wq[0], bq[0], We[0],
                                              Wq[1], bq[1], We[1],
                                              Wq[2], bq[2], We[2]);
    cudaEventRecord(e0, 0);
    cudaStreamWaitEvent(s2, e0, 0);

    // CSR branch on s2
    k_hist<<<(EE + 127) / 128, 128, 0, s2>>>(dst);
    k_scanA<<<NB, 128, 0, s2>>>();
    // main branch: layer-0 GEMM (profiled slot, unchanged = control)
    k_gemm<<<GEMM_BLOCKS, 320, GEMM_SMEM>>>(x, 0, 0, Wq[0], bq[0], Wk[0], bk[0], Wv[0], bv[0], Ws[0], bs[0]);
    k_scanC<<<NB, 128, 0, s2>>>(NB);
    k_scatter<<<(EE + 127) / 128, 128, 0, s2>>>(src, dst);
    cudaEventRecord(e1, s2);
    cudaStreamWaitEvent(0, e1, 0);  // join before agg0

    // layer 0 aggregation (needs gemm0 + scatter)
    k_edge_agg<2><<<AGG_BLOCKS, 256>>>(ea, We[0], nullptr, 1, prelu, 1, 0);

    // layer 1
    k_gemm<<<GEMM_BLOCKS, 320, GEMM_SMEM>>>(nullptr, 1, 1, Wq[1], bq[1], Wk[1], bk[1], Wv[1], bv[1], Ws[1], bs[1]);
    k_edge_agg<2><<<AGG_BLOCKS, 256>>>(ea, We[1], nullptr, 1, prelu, 1, 1);

    // layer 2 (H=1, no prelu, write d_out)
    k_gemm<<<GEMM_BLOCKS, 320, GEMM_SMEM>>>(nullptr, 1, 2, Wq[2], bq[2], Wk[2], bk[2], Wv[2], bv[2], Ws[2], bs[2]);
    k_edge_agg<1><<<AGG_BLOCKS, 256>>>(ea, We[2], out, 0, prelu, 0, 2);

    cudaEventDestroy(e0);
    cudaEventDestroy(e1);
    cudaStreamDestroy(s2);
}

// round 16
// speedup vs baseline: 1.0404x; 1.0404x over previous
#include <cuda_runtime.h>
#include <cuda_fp16.h>

#define NN 50000
#define EE 800000
#define RP_PAD (98 * 512)   // padded rowptr length (98 scan blocks x 512)

typedef unsigned long long ull;

// ---------------- device scratch (static allocations only) ----------------
__device__ float g_q[NN * 64];
__device__ ull   g_kvh[NN * 32];     // fp16x4 per lane: {k0,k1,v0,v1}, row=256B
__device__ float g_skip[NN * 64];
__device__ float g_u[NN * 64];
__device__ float g_h[NN * 64];
__device__ __half g_eah[EE * 32];    // edge_attr in fp16 (converted once)
__device__ float g_M[3][64 * 64];    // folded Wq*We per layer
__device__ float g_bu[3][64];
__device__ int   g_rowptr[RP_PAD];
__device__ int   g_cursor[NN];
__device__ int2  g_se[EE];           // (src, eid) in CSR order
__device__ int   g_part[128];
__device__ int   g_ticket[3];        // warp work-queues, one per layer

// ---------------- packed f32x2 helpers (sm_103a fma.rn.f32x2) -------------
__device__ __forceinline__ ull pk2(float x, float y) {
    ull r; asm("mov.b64 %0, {%1,%2};" : "=l"(r) : "f"(x), "f"(y)); return r;
}
__device__ __forceinline__ ull dup2(float x) { return pk2(x, x); }
__device__ __forceinline__ void up2(ull a, float& x, float& y) {
    asm("mov.b64 {%0,%1}, %2;" : "=f"(x), "=f"(y) : "l"(a));
}
__device__ __forceinline__ ull fma2(ull a, ull b, ull c) {
    ull d; asm("fma.rn.f32x2 %0, %1, %2, %3;" : "=l"(d) : "l"(a), "l"(b), "l"(c)); return d;
}
__device__ __forceinline__ ull add2(ull a, ull b) {
    ull d; asm("add.rn.f32x2 %0, %1, %2;" : "=l"(d) : "l"(a), "l"(b)); return d;
}
__device__ __forceinline__ ull mul2(ull a, ull b) {
    ull d; asm("mul.rn.f32x2 %0, %1, %2;" : "=l"(d) : "l"(a), "l"(b)); return d;
}
// half2 (as uint) -> packed float2 (ull)
__device__ __forceinline__ ull h2f2(unsigned int h) {
    __half2 hh = *reinterpret_cast<__half2*>(&h);
    float2 f = __half22float2(hh);
    return pk2(f.x, f.y);
}

// ---------------- fold body -------------------------------------------------
__device__ __forceinline__ void fold_body(int idx, const float* Wq, const float* bq,
                                          const float* We, int H, int layer) {
    if (idx < 4096) {
        int i = idx >> 6, j = idx & 63;
        float s = 0.f;
        if (H == 2) {
            int h = j >> 5, d = j & 31;
            for (int c = 0; c < 32; c++)
                s += Wq[i * 64 + h * 32 + c] * We[d * 64 + h * 32 + c];
        } else {
            int d = j & 31;
            for (int c = 0; c < 64; c++)
                s += Wq[i * 64 + c] * We[d * 64 + c];
            s *= 0.5f;
        }
        g_M[layer][idx] = s;
    }
    if (idx < 64) {
        int j = idx;
        float s = 0.f;
        if (H == 2) {
            int h = j >> 5, d = j & 31;
            for (int c = 0; c < 32; c++)
                s += bq[h * 32 + c] * We[d * 64 + h * 32 + c];
        } else {
            int d = j & 31;
            for (int c = 0; c < 64; c++)
                s += bq[c] * We[d * 64 + c];
            s *= 0.5f;
        }
        g_bu[layer][j] = s;
    }
}

// zero rowptr (padded) + tickets, and compute ALL THREE layer folds
__global__ void k_zerofold(
    const float* __restrict__ Wq0, const float* __restrict__ bq0, const float* __restrict__ We0,
    const float* __restrict__ Wq1, const float* __restrict__ bq1, const float* __restrict__ We1,
    const float* __restrict__ Wq2, const float* __restrict__ bq2, const float* __restrict__ We2)
{
    int idx = blockIdx.x * blockDim.x + threadIdx.x;
    if (idx < RP_PAD) g_rowptr[idx] = 0;
    if (idx < 3) g_ticket[idx] = 0;
    if (idx < 4096) {
        fold_body(idx, Wq0, bq0, We0, 2, 0);
        fold_body(idx, Wq1, bq1, We1, 2, 1);
        fold_body(idx, Wq2, bq2, We2, 1, 2);
    }
}

// ---------------- edge_attr fp32 -> fp16 (once per launch) -----------------
// thread handles 8 floats: 2x float4 in, 1x uint4 (8 halves) out.
__global__ __launch_bounds__(128) void k_ea2h(const float* __restrict__ ea) {
    int idx = blockIdx.x * blockDim.x + threadIdx.x;  // over EE*32/8 = 3.2M
    if (idx < EE * 4) {
        float4 a = ((const float4*)ea)[idx * 2];
        float4 b = ((const float4*)ea)[idx * 2 + 1];
        uint4 o;
        __half2 h0 = __floats2half2_rn(a.x, a.y);
        __half2 h1 = __floats2half2_rn(a.z, a.w);
        __half2 h2 = __floats2half2_rn(b.x, b.y);
        __half2 h3 = __floats2half2_rn(b.z, b.w);
        o.x = *reinterpret_cast<unsigned int*>(&h0);
        o.y = *reinterpret_cast<unsigned int*>(&h1);
        o.z = *reinterpret_cast<unsigned int*>(&h2);
        o.w = *reinterpret_cast<unsigned int*>(&h3);
        ((uint4*)g_eah)[idx] = o;
    }
}

// ---------------- CSR build (128-thr blocks: co-resident with GEMM) --------
__global__ __launch_bounds__(128) void k_hist(const int* __restrict__ dst) {
    int i = blockIdx.x * blockDim.x + threadIdx.x;
    if (i < EE) atomicAdd(&g_rowptr[dst[i] + 1], 1);
}

__global__ __launch_bounds__(128) void k_scanA() {
    __shared__ int sw[128];
    int b = blockIdx.x, t = threadIdx.x;
    int base = b * 512 + t * 4;
    int4 v = *(const int4*)&g_rowptr[base];
    int e0 = (base + 0 <= NN) ? v.x : 0;
    int e1 = (base + 1 <= NN) ? v.y : 0;
    int e2 = (base + 2 <= NN) ? v.z : 0;
    int e3 = (base + 3 <= NN) ? v.w : 0;
    int s1 = e0 + e1, s2 = s1 + e2, s3 = s2 + e3;
    sw[t] = s3;
    __syncthreads();
#pragma unroll
    for (int off = 1; off < 128; off <<= 1) {
        int tv = (t >= off) ? sw[t - off] : 0;
        __syncthreads();
        sw[t] += tv;
        __syncthreads();
    }
    int excl = (t > 0) ? sw[t - 1] : 0;
    int4 o;
    o.x = excl + e0; o.y = excl + s1; o.z = excl + s2; o.w = excl + s3;
    *(int4*)&g_rowptr[base] = o;
    if (t == 127) g_part[b] = sw[127];
}

__global__ __launch_bounds__(128) void k_scanC(int nb) {
    __shared__ int sp[128];
    int b = blockIdx.x, t = threadIdx.x;
    sp[t] = (t < nb) ? g_part[t] : 0;
    __syncthreads();
#pragma unroll
    for (int off = 1; off < 128; off <<= 1) {
        int tv = (t >= off) ? sp[t - off] : 0;
        __syncthreads();
        sp[t] += tv;
        __syncthreads();
    }
    int excl = (b == 0) ? 0 : sp[b - 1];
    int base = b * 512 + t * 4;
    int4 v = *(const int4*)&g_rowptr[base];
    v.x += excl; v.y += excl; v.z += excl; v.w += excl;
    *(int4*)&g_rowptr[base] = v;
    if (base + 0 < NN) g_cursor[base + 0] = v.x;
    if (base + 1 < NN) g_cursor[base + 1] = v.y;
    if (base + 2 < NN) g_cursor[base + 2] = v.z;
    if (base + 3 < NN) g_cursor[base + 3] = v.w;
}

__global__ __launch_bounds__(128) void k_scatter(const int* __restrict__ src, const int* __restrict__ dst) {
    int i = blockIdx.x * blockDim.x + threadIdx.x;
    if (i < EE) {
        int d = dst[i];
        int pos = atomicAdd(&g_cursor[d], 1);
        g_se[pos] = make_int2(src[i], i);
    }
}

// ---------------- node GEMM: R8 tile + double-buffered x staging -----------
// k/v outputs converted to fp16 in-register and stored as half2.
#define XS_STRIDE (64 * 36)
#define GEMM_SMEM_FLOATS (64 * 320 + 2 * XS_STRIDE)
__global__ __launch_bounds__(320, 2) void k_gemm(
    const float* __restrict__ xin, int in_is_gh, int layer,
    const float* __restrict__ Wq, const float* __restrict__ bq,
    const float* __restrict__ Wk, const float* __restrict__ bk,
    const float* __restrict__ Wv, const float* __restrict__ bv,
    const float* __restrict__ Ws, const float* __restrict__ bs)
{
    extern __shared__ float sm[];
    float* ws = sm;                  // [64][320]
    float* xs = sm + 64 * 320;       // 2 buffers of [64][36]

    const float* x = in_is_gh ? g_h : xin;
    int tid = threadIdx.x;
    int cg = tid >> 3;
    int ng = tid & 7;
    int m  = cg >> 3;
    int c8 = (cg & 7) * 8;
    int nbase = ng * 4;

    {
        const float* W;
        int wm = tid >> 6;
        if      (wm == 0) W = Wq;
        else if (wm == 1) W = Wk;
        else if (wm == 2) W = Wv;
        else if (wm == 3) W = Ws;
        else              W = &g_M[layer][0];
        int wc = tid & 63;
#pragma unroll
        for (int d = 0; d < 64; d++)
            ws[d * 320 + tid] = W[d * 64 + wc];
    }

    ull bacc[4];
    {
        const float* B;
        if      (m == 0) B = bq;
        else if (m == 1) B = bk;
        else if (m == 2) B = bv;
        else if (m == 3) B = bs;
        else             B = g_bu[layer];
#pragma unroll
        for (int cp = 0; cp < 4; cp++)
            bacc[cp] = pk2(B[c8 + 2 * cp], B[c8 + 2 * cp + 1]);
    }

    const int nstrips = (NN + 31) / 32;  // 1563

    int i0 = tid, i1 = tid + 320;
    int nl0 = i0 >> 4, c40 = i0 & 15;
    int nl1 = i1 >> 4, c41 = i1 & 15;

    int strip = blockIdx.x;
    if (strip < nstrips) {
        int n0 = strip * 32;
        {
            int row = n0 + nl0; if (row >= NN) row = NN - 1;
            float4 v = *(const float4*)&x[row * 64 + c40 * 4];
            float* dst = xs;
            dst[(c40 * 4 + 0) * 36 + nl0] = v.x;
            dst[(c40 * 4 + 1) * 36 + nl0] = v.y;
            dst[(c40 * 4 + 2) * 36 + nl0] = v.z;
            dst[(c40 * 4 + 3) * 36 + nl0] = v.w;
        }
        if (i1 < 512) {
            int row = n0 + nl1; if (row >= NN) row = NN - 1;
            float4 v = *(const float4*)&x[row * 64 + c41 * 4];
            float* dst = xs;
            dst[(c41 * 4 + 0) * 36 + nl1] = v.x;
            dst[(c41 * 4 + 1) * 36 + nl1] = v.y;
            dst[(c41 * 4 + 2) * 36 + nl1] = v.z;
            dst[(c41 * 4 + 3) * 36 + nl1] = v.w;
        }
    }

    int buf = 0;
    for (; strip < nstrips; strip += gridDim.x) {
        __syncthreads();

        int nstrip = strip + gridDim.x;
        float4 st0, st1;
        bool do1 = (i1 < 512);
        if (nstrip < nstrips) {
            int n0n = nstrip * 32;
            int row0 = n0n + nl0; if (row0 >= NN) row0 = NN - 1;
            st0 = *(const float4*)&x[row0 * 64 + c40 * 4];
            if (do1) {
                int row1 = n0n + nl1; if (row1 >= NN) row1 = NN - 1;
                st1 = *(const float4*)&x[row1 * 64 + c41 * 4];
            }
        }

        const float* xb = xs + buf * XS_STRIDE;

        ull acc[16];
#pragma unroll
        for (int n = 0; n < 4; n++)
#pragma unroll
            for (int cp = 0; cp < 4; cp++)
                acc[n * 4 + cp] = bacc[cp];

#pragma unroll 8
        for (int d = 0; d < 64; d++) {
            float4 xv = *(const float4*)&xb[d * 36 + nbase];
            const ulonglong2* wp = (const ulonglong2*)&ws[d * 320 + cg * 8];
            ulonglong2 w01 = wp[0];
            ulonglong2 w23 = wp[1];
            ull x0 = dup2(xv.x), x1 = dup2(xv.y), x2 = dup2(xv.z), x3 = dup2(xv.w);
            acc[0]  = fma2(x0, w01.x, acc[0]);
            acc[1]  = fma2(x0, w01.y, acc[1]);
            acc[2]  = fma2(x0, w23.x, acc[2]);
            acc[3]  = fma2(x0, w23.y, acc[3]);
            acc[4]  = fma2(x1, w01.x, acc[4]);
            acc[5]  = fma2(x1, w01.y, acc[5]);
            acc[6]  = fma2(x1, w23.x, acc[6]);
            acc[7]  = fma2(x1, w23.y, acc[7]);
            acc[8]  = fma2(x2, w01.x, acc[8]);
            acc[9]  = fma2(x2, w01.y, acc[9]);
            acc[10] = fma2(x2, w23.x, acc[10]);
            acc[11] = fma2(x2, w23.y, acc[11]);
            acc[12] = fma2(x3, w01.x, acc[12]);
            acc[13] = fma2(x3, w01.y, acc[13]);
            acc[14] = fma2(x3, w23.x, acc[14]);
            acc[15] = fma2(x3, w23.y, acc[15]);
        }

        int n0 = strip * 32;
#pragma unroll
        for (int n = 0; n < 4; n++) {
            int row = n0 + nbase + n; if (row >= NN) row = NN - 1;
            ull* a = &acc[n * 4];
            if (m == 1 || m == 2) {
                int boff = (m == 1) ? 0 : 4;  // k low half, v high half of ull
#pragma unroll
                for (int cp = 0; cp < 4; cp++) {
                    float ax, ay; up2(a[cp], ax, ay);
                    __half2 h = __floats2half2_rn(ax, ay);
                    *reinterpret_cast<__half2*>(
                        (char*)&g_kvh[row * 32 + (c8 / 2 + cp)] + boff) = h;
                }
            } else {
                float* O = (m == 0) ? g_q : ((m == 3) ? g_skip : g_u);
                ulonglong2 s0; s0.x = a[0]; s0.y = a[1];
                ulonglong2 s1; s1.x = a[2]; s1.y = a[3];
                *(ulonglong2*)&O[row * 64 + c8] = s0;
                *(ulonglong2*)&O[row * 64 + c8 + 4] = s1;
            }
        }

        if (nstrip < nstrips) {
            float* dst = xs + (1 - buf) * XS_STRIDE;
            dst[(c40 * 4 + 0) * 36 + nl0] = st0.x;
            dst[(c40 * 4 + 1) * 36 + nl0] = st0.y;
            dst[(c40 * 4 + 2) * 36 + nl0] = st0.z;
            dst[(c40 * 4 + 3) * 36 + nl0] = st0.w;
            if (do1) {
                dst[(c41 * 4 + 0) * 36 + nl1] = st1.x;
                dst[(c41 * 4 + 1) * 36 + nl1] = st1.y;
                dst[(c41 * 4 + 2) * 36 + nl1] = st1.z;
                dst[(c41 * 4 + 3) * 36 + nl1] = st1.w;
            }
        }
        buf ^= 1;
    }
}

// ---------------- fused edge aggregation: persistent warp-ticket -----------
// fp16 gather payloads: 8B kv + 4B ea per lane per edge (halved L2 traffic).
template <int H>
__global__ __launch_bounds__(256, 6) void k_edge_agg(
    const float* __restrict__ We,
    float* __restrict__ out, int out_is_gh,
    const float* __restrict__ prelu, int apply_prelu, int layer)
{
    __shared__ __align__(16) float we_s[32 * 64];
    __shared__ __align__(16) float zs[8][64];

    int tid = threadIdx.x;
    int lane = tid & 31;
    int wslot = tid >> 5;

    for (int idx = tid; idx < 2048; idx += 256) we_s[idx] = We[idx];
    __syncthreads();

    float* o = out_is_gh ? g_h : out;
    const float scale = (H == 2) ? 0.17677669529663687f : 0.125f;
    const int eaoff = (2 * lane) & 31;
    const float aprelu = apply_prelu ? *prelu : 1.0f;

    int nraw = 0;
    if (lane == 0) nraw = atomicAdd(&g_ticket[layer], 1);
    int n = __shfl_sync(0xffffffffu, nraw, 0);

    while (n < NN) {
        if (lane == 0) nraw = atomicAdd(&g_ticket[layer], 1);

        ull q2 = *(const ull*)&g_q[n * 64 + 2 * lane];
        ull u2 = *(const ull*)&g_u[n * 64 + 2 * lane];

        ull accv = 0, accz = 0;
        float s = 0.f;

        int beg = g_rowptr[n], end = g_rowptr[n + 1];
        int deg = end - beg;
        int npair = deg >> 1;

        uint2 kv0 = make_uint2(0, 0), kv1 = make_uint2(0, 0);
        unsigned int ea0 = 0, ea1 = 0;

        if (npair > 0) {
            int2 i0 = g_se[beg], i1 = g_se[beg + 1];
            kv0 = *(const uint2*)&g_kvh[i0.x * 32 + lane];
            kv1 = *(const uint2*)&g_kvh[i1.x * 32 + lane];
            ea0 = *(const unsigned int*)&g_eah[(long)i0.y * 32 + eaoff];
            ea1 = *(const unsigned int*)&g_eah[(long)i1.y * 32 + eaoff];
        }

        int i = beg;
        for (int p = 0; p < npair; p++) {
            uint2 kva = kv0, kvb = kv1;
            unsigned int eda = ea0, edb = ea1;
            int j = i + 2;

            if (p + 1 < npair) {
                int2 i0 = g_se[j], i1 = g_se[j + 1];
                kv0 = *(const uint2*)&g_kvh[i0.x * 32 + lane];
                kv1 = *(const uint2*)&g_kvh[i1.x * 32 + lane];
                ea0 = *(const unsigned int*)&g_eah[(long)i0.y * 32 + eaoff];
                ea1 = *(const unsigned int*)&g_eah[(long)i1.y * 32 + eaoff];
            }

            ull ka = h2f2(kva.x), va = h2f2(kva.y);
            ull kb = h2f2(kvb.x), vb = h2f2(kvb.y);
            ull e2a = h2f2(eda),  e2b = h2f2(edb);

            ull pa = add2(mul2(q2, ka), mul2(u2, e2a));
            ull pb = add2(mul2(q2, kb), mul2(u2, e2b));
            float ax0, ay0, bx0, by0;
            up2(pa, ax0, ay0);
            up2(pb, bx0, by0);
            float pla = ax0 + ay0;
            float plb = bx0 + by0;
            pla += __shfl_xor_sync(0xffffffffu, pla, 1);
            plb += __shfl_xor_sync(0xffffffffu, plb, 1);
            pla += __shfl_xor_sync(0xffffffffu, pla, 2);
            plb += __shfl_xor_sync(0xffffffffu, plb, 2);
            pla += __shfl_xor_sync(0xffffffffu, pla, 4);
            plb += __shfl_xor_sync(0xffffffffu, plb, 4);
            pla += __shfl_xor_sync(0xffffffffu, pla, 8);
            plb += __shfl_xor_sync(0xffffffffu, plb, 8);
            if (H == 1) {
                pla += __shfl_xor_sync(0xffffffffu, pla, 16);
                plb += __shfl_xor_sync(0xffffffffu, plb, 16);
            }

            float w0 = __expf(pla * scale);
            float w1 = __expf(plb * scale);
            s += w0 + w1;

            ull w02 = dup2(w0), w12 = dup2(w1);
            accv = add2(accv, fma2(w02, va, mul2(w12, vb)));
            accz = add2(accz, fma2(w02, e2a, mul2(w12, e2b)));
            i = j;
        }

        for (; i < end; i++) {
            int2 t = g_se[i];
            uint2 kva = *(const uint2*)&g_kvh[t.x * 32 + lane];
            unsigned int eda = *(const unsigned int*)&g_eah[(long)t.y * 32 + eaoff];
            ull ka = h2f2(kva.x), va = h2f2(kva.y), e2a = h2f2(eda);
            ull pa = add2(mul2(q2, ka), mul2(u2, e2a));
            float ax0, ay0; up2(pa, ax0, ay0);
            float pla = ax0 + ay0;
            pla += __shfl_xor_sync(0xffffffffu, pla, 1);
            pla += __shfl_xor_sync(0xffffffffu, pla, 2);
            pla += __shfl_xor_sync(0xffffffffu, pla, 4);
            pla += __shfl_xor_sync(0xffffffffu, pla, 8);
            if (H == 1) pla += __shfl_xor_sync(0xffffffffu, pla, 16);
            float w0 = __expf(pla * scale);
            s += w0;
            ull w02 = dup2(w0);
            accv = fma2(w02, va, accv);
            accz = fma2(w02, e2a, accz);
        }

        float zx, zy; up2(accz, zx, zy);
        zs[wslot][2 * lane] = zx;
        zs[wslot][2 * lane + 1] = zy;
        __syncwarp();

        ull ze = 0;
        int base = (H == 2) ? ((lane >> 4) * 32) : 0;
#pragma unroll
        for (int d = 0; d < 32; d++) {
            ull wp = *(const ull*)&we_s[d * 64 + 2 * lane];
            ze = fma2(dup2(zs[wslot][base + d]), wp, ze);
        }
        __syncwarp();

        ull skip2 = *(const ull*)&g_skip[n * 64 + 2 * lane];
        float inv = (s > 0.f) ? 1.f / s : 0.f;
        float avx, avy; up2(accv, avx, avy);
        float ex, ey; up2(ze, ex, ey);
        float sx, sy; up2(skip2, sx, sy);
        float ox = (avx + ex) * inv + sx;
        float oy = (avy + ey) * inv + sy;
        if (apply_prelu) {
            ox = (ox >= 0.f) ? ox : aprelu * ox;
            oy = (oy >= 0.f) ? oy : aprelu * oy;
        }
        *(float2*)&o[n * 64 + 2 * lane] = make_float2(ox, oy);

        n = __shfl_sync(0xffffffffu, nraw, 0);
    }
}

// ---------------- launch ----------------------------------------------------
extern "C" void kernel_launch(void* const* d_in, const int* in_sizes, int n_in,
                              void* d_out, int out_size)
{
    const float* x  = (const float*)d_in[0];
    const float* ea = (const float*)d_in[1];
    const int*   ei = (const int*)d_in[2];
    const int* src = ei;
    const int* dst = ei + EE;

    const float *Wq[3], *bq[3], *Wk[3], *bk[3], *Wv[3], *bv[3], *We[3], *Ws[3], *bs[3];
    for (int l = 0; l < 3; l++) {
        int b = 3 + 9 * l;
        Wq[l] = (const float*)d_in[b + 0];
        bq[l] = (const float*)d_in[b + 1];
        Wk[l] = (const float*)d_in[b + 2];
        bk[l] = (const float*)d_in[b + 3];
        Wv[l] = (const float*)d_in[b + 4];
        bv[l] = (const float*)d_in[b + 5];
        We[l] = (const float*)d_in[b + 6];
        Ws[l] = (const float*)d_in[b + 7];
        bs[l] = (const float*)d_in[b + 8];
    }
    const float* prelu = (const float*)d_in[30];
    float* out = (float*)d_out;

    const int NB = 98;            // scan blocks (512 elems each)
    const int AGG_BLOCKS = 888;   // 6 blocks/SM x 148 SMs
    const int GEMM_BLOCKS = 296;
    const int GEMM_SMEM = GEMM_SMEM_FLOATS * 4;  // 100352 B

    cudaFuncSetAttribute(k_gemm, cudaFuncAttributeMaxDynamicSharedMemorySize, GEMM_SMEM);

    // fork/join: CSR chain + ea->fp16 conversion overlap gemm0
    cudaStream_t s2;
    cudaStreamCreateWithFlags(&s2, cudaStreamNonBlocking);
    cudaEvent_t e0, e1;
    cudaEventCreateWithFlags(&e0, cudaEventDisableTiming);
    cudaEventCreateWithFlags(&e1, cudaEventDisableTiming);

    // 1: zero rowptr+tickets + all folds (root of both branches)
    k_zerofold<<<(RP_PAD + 255) / 256, 256>>>(Wq[0], bq[0], We[0],
                                              Wq[1], bq[1], We[1],
                                              Wq[2], bq[2], We[2]);
    cudaEventRecord(e0, 0);
    cudaStreamWaitEvent(s2, e0, 0);

    // side branch on s2: ea conversion + CSR
    k_ea2h<<<(EE * 4 + 127) / 128, 128, 0, s2>>>(ea);
    k_hist<<<(EE + 127) / 128, 128, 0, s2>>>(dst);
    // main branch: layer-0 GEMM (profiled slot 4, control)
    k_gemm<<<GEMM_BLOCKS, 320, GEMM_SMEM>>>(x, 0, 0, Wq[0], bq[0], Wk[0], bk[0], Wv[0], bv[0], Ws[0], bs[0]);
    k_scanA<<<NB, 128, 0, s2>>>();
    k_scanC<<<NB, 128, 0, s2>>>(NB);
    k_scatter<<<(EE + 127) / 128, 128, 0, s2>>>(src, dst);
    cudaEventRecord(e1, s2);
    cudaStreamWaitEvent(0, e1, 0);  // join before agg0

    // layer 0 aggregation
    k_edge_agg<2><<<AGG_BLOCKS, 256>>>(We[0], nullptr, 1, prelu, 1, 0);

    // layer 1
    k_gemm<<<GEMM_BLOCKS, 320, GEMM_SMEM>>>(nullptr, 1, 1, Wq[1], bq[1], Wk[1], bk[1], Wv[1], bv[1], Ws[1], bs[1]);
    k_edge_agg<2><<<AGG_BLOCKS, 256>>>(We[1], nullptr, 1, prelu, 1, 1);

    // layer 2 (H=1, no prelu, write d_out)
    k_gemm<<<GEMM_BLOCKS, 320, GEMM_SMEM>>>(nullptr, 1, 2, Wq[2], bq[2], Wk[2], bk[2], Wv[2], bv[2], Ws[2], bs[2]);
    k_edge_agg<1><<<AGG_BLOCKS, 256>>>(We[2], out, 0, prelu, 0, 2);

    cudaEventDestroy(e0);
    cudaEventDestroy(e1);
    cudaStreamDestroy(s2);
}